// round 12
// baseline (speedup 1.0000x reference)
#include <cuda_runtime.h>
#include <math.h>

#define NW 14
#define NL 4
#define NSTATE (1 << NW)
#define THREADS 1024
#define AMPS 16
#define PI_F 3.14159265358979323846f

typedef unsigned long long u64;

// ---------- packed f32x2 helpers ----------
__device__ __forceinline__ u64 pk(float lo, float hi) {
    u64 r; asm("mov.b64 %0, {%1, %2};" : "=l"(r) : "f"(lo), "f"(hi)); return r;
}
__device__ __forceinline__ void unpk(u64 a, float& lo, float& hi) {
    asm("mov.b64 {%0, %1}, %2;" : "=f"(lo), "=f"(hi) : "l"(a));
}
__device__ __forceinline__ u64 swp(u64 a) {
    float lo, hi; unpk(a, lo, hi);
    u64 r; asm("mov.b64 %0, {%1, %2};" : "=l"(r) : "f"(hi), "f"(lo)); return r;
}
__device__ __forceinline__ u64 ffma2_(u64 a, u64 b, u64 c) {
    u64 d; asm("fma.rn.f32x2 %0, %1, %2, %3;" : "=l"(d) : "l"(a), "l"(b), "l"(c));
    return d;
}
__device__ __forceinline__ u64 fmul2_(u64 a, u64 b) {
    u64 d; asm("mul.rn.f32x2 %0, %1, %2;" : "=l"(d) : "l"(a), "l"(b));
    return d;
}

__device__ __forceinline__ float2 cmul(float2 a, float2 b) {
    return make_float2(a.x * b.x - a.y * b.y, a.x * b.y + a.y * b.x);
}

// Swizzle (R3-validated): u64-slot bank = low 4 bits; XOR with bits 4-7.
__device__ __forceinline__ int sw(int i) { return i ^ ((i >> 4) & 15); }

// Tangent-form RY butterfly on local bit L of r[16]:
//   y0 = x0 - t*x1, y1 = x1 + t*x0  (uniform cos deferred to output scale)
template <int L>
__device__ __forceinline__ void apply_gateT(u64* r, u64 Tp, u64 Tn) {
#pragma unroll
    for (int p = 0; p < 8; p++) {
        const int lm = (1 << L) - 1;
        const int j0 = ((p & ~lm) << 1) | (p & lm);
        const int j1 = j0 | (1 << L);
        u64 x0 = r[j0], x1 = r[j1];
        r[j0] = ffma2_(Tn, x1, x0);
        r[j1] = ffma2_(Tp, x0, x1);
    }
}

// Per-amp phase multiply: y = z*x, z as B=(zr,zr), P=(-zi,+zi).
__device__ __forceinline__ u64 dphase(u64 x, u64 B, u64 P) {
    return ffma2_(B, x, fmul2_(P, swp(x)));
}

// CNOT chain as GF(2)-linear basis permutation.
// Index bit k = wire (13-k). dst_k = xor(src k..13) (k<=12); dst_13 = xor(src 0..12).
__device__ __forceinline__ unsigned cnot_perm(unsigned i) {
    unsigned s = i;
    s ^= s >> 1; s ^= s >> 2; s ^= s >> 4; s ^= s >> 8;
    return (s & 0x1FFFu) | (((s ^ (i >> 13)) & 1u) << 13);
}

__global__ __launch_bounds__(THREADS, 1)
void vqc_kernel(const float* __restrict__ x_raw,
                const float* __restrict__ angles,
                float* __restrict__ out) {
    extern __shared__ unsigned char smem[];
    u64*    sv   = (u64*)smem;                 // [NSTATE]
    u64*    sU   = sv + NSTATE;                // [NL*NW*2]  Tp,Tn
    u64*    sTB  = sU + NL * NW * 2;           // [3*16] boundary diag j-table B
    u64*    sTP  = sTB + 3 * 16;               // [3*16] boundary diag j-table P
    float2* sT0  = (float2*)(sTP + 3 * 16);    // [16]  layer-0 D_R j-table
    float2* senc = sT0 + 16;                   // [NW]
    float2* sSb  = senc + NW;                  // [3]  e^{i sum(beta wires 4..13)}
    float2* sZ13 = sSb + 3;                    // [3]  e^{i beta(wire0)}
    float*  sAL  = (float*)(sZ13 + 3);         // [NL*NW] ZYZ alpha
    float*  sBE  = sAL + NL * NW;              // [NL*NW] ZYZ beta
    float*  sC   = sBE + NL * NW;              // [NL*NW] ZYZ cos
    float*  sS2  = sC + NL * NW;               // [1] total scale^2
    float*  sred = sS2 + 1;                    // [32]

    const int t = threadIdx.x;                 // 10 bits = i bits 0..9
    const int b = blockIdx.x;

    // suffix-xor of t (10 bits): bit m = xor(t_m..t_9)
    int stx = t;
    stx ^= stx >> 1; stx ^= stx >> 2; stx ^= stx >> 4; stx ^= stx >> 8;
    // per-thread GF(2)-linear parts
    const int pts     = sw((int)cnot_perm((unsigned)t));   // scatter offset
    const int ptp     = __popc(t) & 1;                     // parity of t
    // (ptp also = measurement thread-sign: dst13 = par(i bits 0..12) and
    //  bits 0..9 are t; j-part handled per-amp.)

    // ---- phase 1: encoding factors + ZYZ decomposition ----
    if (t < NW) {
        float a = tanhf(x_raw[b * NW + t]) * PI_F;
        senc[t] = make_float2(cosf(0.5f * a), sinf(0.5f * a));
    }
    if (t < NL * NW) {
        const int k = t / NW, w = t % NW;
        const float a0 = angles[(k * NW + w) * 3 + 0];
        const float a1 = angles[(k * NW + w) * 3 + 1];
        const float a2 = angles[(k * NW + w) * 3 + 2];
        const float c0 = cosf(0.5f * a0), s0 = sinf(0.5f * a0);
        const float c1 = cosf(0.5f * a1), s1 = sinf(0.5f * a1);
        float2 m00, m10;
        {
            const float2 ry00 = make_float2(c1, 0.f), ry01 = make_float2(-s1, 0.f);
            const float2 rx00 = make_float2(c0, 0.f), rx10 = make_float2(0.f, -s0);
            m00 = make_float2(ry00.x * rx00.x + ry01.x * rx10.x - ry01.y * rx10.y,
                              ry00.x * rx00.y + ry01.x * rx10.y + ry01.y * rx10.x);
            const float2 ry10 = make_float2(s1, 0.f), ry11 = make_float2(c1, 0.f);
            m10 = make_float2(ry10.x * rx00.x + ry11.x * rx10.x - ry11.y * rx10.y,
                              ry10.x * rx00.y + ry11.x * rx10.y + ry11.y * rx10.x);
        }
        const float2 em = make_float2(cosf(0.5f * a2), -sinf(0.5f * a2));
        const float2 ep = make_float2(em.x, -em.y);
        float2 u00 = cmul(em, m00);
        float2 u10 = cmul(ep, m10);
        float c  = sqrtf(u00.x * u00.x + u00.y * u00.y);
        float s  = sqrtf(u10.x * u10.x + u10.y * u10.y);
        float pp = -atan2f(u00.y, u00.x);
        float pm =  atan2f(u10.y, u10.x);
        sU[t * 2 + 0] = pk(s / c, s / c);
        sU[t * 2 + 1] = pk(-s / c, -s / c);
        sAL[t] = pp + pm;
        sBE[t] = pp - pm;
        sC[t]  = c;
    }
    __syncthreads();

    // ---- phase 2: diagonal tables + global scale ----
    if (t < 16) {
        // layer-0 D_R j-table (pass-A layout: j bit q = i bit q = wire 13-q)
        float a = 0.f;
#pragma unroll
        for (int q = 0; q < 4; q++)
            if ((t >> q) & 1) a += sBE[13 - q];
        sT0[t] = make_float2(cosf(a), sinf(a));
    } else if (t >= 32 && t < 80) {
        // boundary bk j-tables (pass-D layout: j bit q = i bit 10+q = wire 3-q)
        const int bk = (t - 32) >> 4, j = t & 15;
        int sxj = j; sxj ^= sxj >> 1; sxj ^= sxj >> 2;   // suffix xor, 4 bits
        float a = 0.f;
#pragma unroll
        for (int q = 0; q < 4; q++)
            if ((j >> q) & 1) a += sAL[bk * NW + 3 - q];        // D_L(k)
#pragma unroll
        for (int r = 0; r < 3; r++)                              // dst bits 10..12
            if ((sxj >> r) & 1) a += sBE[(bk + 1) * NW + 3 - r]; // D_R(k+1)
        sTB[bk * 16 + j] = pk(cosf(a), cosf(a));
        sTP[bk * 16 + j] = pk(-sinf(a), sinf(a));
    } else if (t >= 128 && t < 131) {
        const int bk = t - 128;
        float sb = 0.f;
#pragma unroll
        for (int m = 0; m < 10; m++) sb += sBE[(bk + 1) * NW + 13 - m];
        sSb[bk] = make_float2(cosf(sb), sinf(sb));
        float c13 = sBE[(bk + 1) * NW + 0];
        sZ13[bk] = make_float2(cosf(c13), sinf(c13));
    } else if (t == 131) {
        float S = 1.f;
#pragma unroll
        for (int i = 0; i < NL * NW; i++) S *= sC[i];
        sS2[0] = S * S;
    }
    __syncthreads();

    u64 r[AMPS];

    for (int k = 0; k < NL; k++) {
        const u64* Gk = sU + k * NW * 2;

        // ===== Pass A: i = (t<<4)|j. j bits 0..3 = wires 13,12,11,10 =====
        if (k == 0) {
            // product state in registers; wire w<=9 at t bit (9-w)
            float v[AMPS];
            float common = 1.f;
#pragma unroll
            for (int w = 0; w < 10; w++) {
                float2 cs = senc[w];
                common *= ((t >> (9 - w)) & 1) ? cs.y : cs.x;
            }
            v[0] = common;
#pragma unroll
            for (int st = 0; st < 4; st++) {   // final: j bit 0 = wire 13
                float2 cs = senc[10 + st];
#pragma unroll
                for (int kk = (1 << st) - 1; kk >= 0; kk--) {
                    float vv = v[kk];
                    v[2 * kk + 1] = vv * cs.y;
                    v[2 * kk]     = vv * cs.x;
                }
            }
            // layer-0 D_R: thread part (i bit 4+m = t_m = wire 9-m)
            float th0 = 0.f;
#pragma unroll
            for (int m = 0; m < 10; m++)
                if ((t >> m) & 1) th0 += sBE[9 - m];
            float s0t, c0t; __sincosf(th0, &s0t, &c0t);
            const float2 z0 = make_float2(c0t, s0t);
#pragma unroll
            for (int j = 0; j < AMPS; j++) {
                float2 zj = cmul(z0, sT0[j]);
                r[j] = pk(v[j] * zj.x, v[j] * zj.y);
            }
        } else {
#pragma unroll
            for (int j = 0; j < AMPS; j++) r[j] = sv[sw((t << 4) | j)];
        }
        apply_gateT<0>(r, Gk[13 * 2], Gk[13 * 2 + 1]);
        apply_gateT<1>(r, Gk[12 * 2], Gk[12 * 2 + 1]);
        apply_gateT<2>(r, Gk[11 * 2], Gk[11 * 2 + 1]);
        apply_gateT<3>(r, Gk[10 * 2], Gk[10 * 2 + 1]);
#pragma unroll
        for (int j = 0; j < AMPS; j++) sv[sw((t << 4) | j)] = r[j];
        __syncwarp();   // A region and B readers stay within the warp

        // ===== Pass B: i = ((t>>4)<<8)|(j<<4)|(t&15). j = wires 9,8,7,6 =====
        {
            const int hi = (t >> 4) << 8, lo = t & 15;
#pragma unroll
            for (int j = 0; j < AMPS; j++) r[j] = sv[sw(hi | (j << 4) | lo)];
            apply_gateT<0>(r, Gk[9 * 2], Gk[9 * 2 + 1]);
            apply_gateT<1>(r, Gk[8 * 2], Gk[8 * 2 + 1]);
            apply_gateT<2>(r, Gk[7 * 2], Gk[7 * 2 + 1]);
            apply_gateT<3>(r, Gk[6 * 2], Gk[6 * 2 + 1]);
#pragma unroll
            for (int j = 0; j < AMPS; j++) sv[sw(hi | (j << 4) | lo)] = r[j];
        }
        __syncthreads();

        // ===== Pass C: i = ((t>>8)<<12)|(j<<8)|(t&255). j = wires 5,4,3,2 =====
        {
            const int hi = (t >> 8) << 12, lo = t & 255;
#pragma unroll
            for (int j = 0; j < AMPS; j++) r[j] = sv[sw(hi | (j << 8) | lo)];
            apply_gateT<0>(r, Gk[5 * 2], Gk[5 * 2 + 1]);
            apply_gateT<1>(r, Gk[4 * 2], Gk[4 * 2 + 1]);
            apply_gateT<2>(r, Gk[3 * 2], Gk[3 * 2 + 1]);
            apply_gateT<3>(r, Gk[2 * 2], Gk[2 * 2 + 1]);
#pragma unroll
            for (int j = 0; j < AMPS; j++) sv[sw(hi | (j << 8) | lo)] = r[j];
        }
        __syncthreads();

        // ===== Pass D: i = (j<<10)|t. j bits 2,3 = wires 1,0 (bits 0,1 inert) =====
        if (k < NL - 1) {
            // combined diagonal D_R(k+1) o P o D_L(k) constants (hide MUFU)
            float thL = 0.f, thB = 0.f;
#pragma unroll
            for (int m = 0; m < 10; m++) {
                if ((t >> m) & 1)   thL += sAL[k * NW + 13 - m];
                if ((stx >> m) & 1) thB += sBE[(k + 1) * NW + 13 - m];
            }
            float sa, ca, sb2, cb2;
            __sincosf(thL, &sa, &ca);
            __sincosf(thB, &sb2, &cb2);
            const float2 zA = make_float2(ca, sa);
            float2 A0 = cmul(zA, make_float2(cb2, sb2));                // pj=0
            float2 A1 = cmul(cmul(zA, make_float2(cb2, -sb2)), sSb[k]); // pj=1
            const float2 z13 = sZ13[k];
            float2 A0x = cmul(A0, z13), A1x = cmul(A1, z13);
            // V[pj][f0] with flag = ptp ^ pj ^ j3; fold runtime ptp here:
            float2 V00, V01, V10, V11;
            if (ptp) { V00 = A0x; V01 = A0;  V10 = A1x; V11 = A1;  }
            else     { V00 = A0;  V01 = A0x; V10 = A1;  V11 = A1x; }
            const u64 B00 = pk(V00.x, V00.x), P00 = pk(-V00.y, V00.y);
            const u64 B01 = pk(V01.x, V01.x), P01 = pk(-V01.y, V01.y);
            const u64 B10 = pk(V10.x, V10.x), P10 = pk(-V10.y, V10.y);
            const u64 B11 = pk(V11.x, V11.x), P11 = pk(-V11.y, V11.y);
            const u64* TBk = sTB + k * 16;
            const u64* TPk = sTP + k * 16;

#pragma unroll
            for (int j = 0; j < AMPS; j++) r[j] = sv[sw((j << 10) | t)];
            apply_gateT<2>(r, Gk[1 * 2], Gk[1 * 2 + 1]);
            apply_gateT<3>(r, Gk[0 * 2], Gk[0 * 2 + 1]);
#pragma unroll
            for (int j = 0; j < AMPS; j++) {
                const int pj = __popc(j) & 1;              // compile-time
                const int f0 = pj ^ ((j >> 3) & 1);        // compile-time
                const u64 WB = pj ? (f0 ? B11 : B10) : (f0 ? B01 : B00);
                const u64 WP = pj ? (f0 ? P11 : P10) : (f0 ? P01 : P00);
                r[j] = dphase(dphase(r[j], TBk[j], TPk[j]), WB, WP);
            }
            // all D-loads must complete CTA-wide before any scatter store
            __syncthreads();
#pragma unroll
            for (int j = 0; j < AMPS; j++)
                sv[sw((int)cnot_perm((unsigned)(j << 10))) ^ pts] = r[j];
            __syncthreads();
        } else {
#pragma unroll
            for (int j = 0; j < AMPS; j++) r[j] = sv[sw((j << 10) | t)];
            apply_gateT<2>(r, Gk[1 * 2], Gk[1 * 2 + 1]);
            apply_gateT<3>(r, Gk[0 * 2], Gk[0 * 2 + 1]);
            // <Z0>: sign = par(src bits 0..12) = par(t) ^ par(j bits 0..2)
            float acc = 0.f;
#pragma unroll
            for (int j = 0; j < AMPS; j++) {
                float re, im; unpk(r[j], re, im);
                float vv = fmaf(re, re, im * im);
                acc += (__popc(j & 7) & 1) ? -vv : vv;
            }
            acc = ptp ? -acc : acc;
#pragma unroll
            for (int off = 16; off; off >>= 1)
                acc += __shfl_xor_sync(0xffffffffu, acc, off);
            if ((t & 31) == 0) sred[t >> 5] = acc;
            __syncthreads();
            if (t < 32) {
                float v = sred[t];
#pragma unroll
                for (int off = 16; off; off >>= 1)
                    v += __shfl_xor_sync(0xffffffffu, v, off);
                if (t == 0) out[b] = v * sS2[0];
            }
        }
    }
}

extern "C" void kernel_launch(void* const* d_in, const int* in_sizes, int n_in,
                              void* d_out, int out_size) {
    const float* x   = (const float*)d_in[0];
    const float* ang = (const float*)d_in[1];
    if (n_in >= 2 && in_sizes[0] == NL * NW * 3 && in_sizes[1] != NL * NW * 3) {
        const float* tmp = x; x = ang; ang = tmp;
    }
    float* out = (float*)d_out;

    const int smem_bytes =
        (NSTATE + NL * NW * 2 + 2 * 3 * 16) * 8      // sv, sU, sTB, sTP
        + (16 + NW + 3 + 3) * 8                      // sT0, senc, sSb, sZ13
        + (3 * NL * NW + 1 + 32) * 4;                // sAL, sBE, sC, sS2, sred
    cudaFuncSetAttribute(vqc_kernel, cudaFuncAttributeMaxDynamicSharedMemorySize,
                         smem_bytes);
    vqc_kernel<<<1024, THREADS, smem_bytes>>>(x, ang, out);
}

// round 13
// speedup vs baseline: 1.2317x; 1.2317x over previous
#include <cuda_runtime.h>
#include <math.h>

#define NW 14
#define NL 4
#define NSTATE (1 << NW)
#define THREADS 512
#define PI_F 3.14159265358979323846f

typedef unsigned long long u64;

// ---------- packed f32x2 helpers ----------
__device__ __forceinline__ u64 pk(float lo, float hi) {
    u64 r; asm("mov.b64 %0, {%1, %2};" : "=l"(r) : "f"(lo), "f"(hi)); return r;
}
__device__ __forceinline__ void unpk(u64 a, float& lo, float& hi) {
    asm("mov.b64 {%0, %1}, %2;" : "=f"(lo), "=f"(hi) : "l"(a));
}
__device__ __forceinline__ u64 swp(u64 a) {
    float lo, hi; unpk(a, lo, hi);
    u64 r; asm("mov.b64 %0, {%1, %2};" : "=l"(r) : "f"(hi), "f"(lo)); return r;
}
__device__ __forceinline__ u64 ffma2_(u64 a, u64 b, u64 c) {
    u64 d; asm("fma.rn.f32x2 %0, %1, %2, %3;" : "=l"(d) : "l"(a), "l"(b), "l"(c));
    return d;
}
__device__ __forceinline__ u64 fmul2_(u64 a, u64 b) {
    u64 d; asm("mul.rn.f32x2 %0, %1, %2;" : "=l"(d) : "l"(a), "l"(b));
    return d;
}

__device__ __forceinline__ float2 cmul(float2 a, float2 b) {
    return make_float2(a.x * b.x - a.y * b.y, a.x * b.y + a.y * b.x);
}

// Tangent-form RY butterfly on local bit L of a full 32-amp block.
template <int L>
__device__ __forceinline__ void apply_gateT(u64* r, u64 Tp, u64 Tn) {
#pragma unroll
    for (int p = 0; p < 16; p++) {
        const int lm = (1 << L) - 1;
        const int j0 = ((p & ~lm) << 1) | (p & lm);
        const int j1 = j0 | (1 << L);
        u64 x0 = r[j0], x1 = r[j1];
        r[j0] = ffma2_(Tn, x1, x0);
        r[j1] = ffma2_(Tp, x0, x1);
    }
}

// Tangent-form RY butterfly on local bit L (0..3) of a 16-amp half-block.
template <int L>
__device__ __forceinline__ void apply_gateT_h(u64* h, u64 Tp, u64 Tn) {
#pragma unroll
    for (int p = 0; p < 8; p++) {
        const int lm = (1 << L) - 1;
        const int j0 = ((p & ~lm) << 1) | (p & lm);
        const int j1 = j0 | (1 << L);
        u64 x0 = h[j0], x1 = h[j1];
        h[j0] = ffma2_(Tn, x1, x0);
        h[j1] = ffma2_(Tp, x0, x1);
    }
}

// Per-amp phase multiply: y = z*x, z as B=(zr,zr), P=(-zi,+zi).
__device__ __forceinline__ u64 dphase(u64 x, u64 B, u64 P) {
    return ffma2_(B, x, fmul2_(P, swp(x)));
}

// CNOT chain as GF(2)-linear basis permutation.
__device__ __forceinline__ unsigned cnot_perm(unsigned i) {
    unsigned s = i;
    s ^= s >> 1; s ^= s >> 2; s ^= s >> 4; s ^= s >> 8;
    return (s & 0x1FFFu) | (((s ^ (i >> 13)) & 1u) << 13);
}

// Scatter swizzle (pass-A layout): slot(i) = i ^ ((i>>5)&31). GF(2)-linear.
__device__ __forceinline__ int sw(int i) { return i ^ ((i >> 5) & 31); }

__global__ __launch_bounds__(THREADS, 1)
void vqc_kernel(const float* __restrict__ x_raw,
                const float* __restrict__ angles,
                float* __restrict__ out) {
    extern __shared__ unsigned char smem[];
    u64*    sv   = (u64*)smem;                 // [NSTATE]
    u64*    sU   = sv + NSTATE;                // [NL*NW*2]  Tp,Tn
    u64*    sTB  = sU + NL * NW * 2;           // [3*32] boundary diag table B
    u64*    sTP  = sTB + 3 * 32;               // [3*32] boundary diag table P
    float2* sT0  = (float2*)(sTP + 3 * 32);    // [32]  layer-0 D_R j-table
    float2* senc = sT0 + 32;                   // [NW]
    float2* sSb  = senc + NW;                  // [3]  e^{i sum(beta 5..13)}
    float2* sZ13 = sSb + 3;                    // [3]  e^{i beta(wire0)}
    float*  sAL  = (float*)(sZ13 + 3);         // [NL*NW] ZYZ alpha
    float*  sBE  = sAL + NL * NW;              // [NL*NW] ZYZ beta
    float*  sC   = sBE + NL * NW;              // [NL*NW] ZYZ cos
    float*  sS2  = sC + NL * NW;               // [1] total scale^2
    float*  sred = sS2 + 1;                    // [16]

    const int tid = threadIdx.x;
    const int b   = blockIdx.x;

    // suffix-xor of tid (9 bits)
    int stx = tid;
    stx ^= stx >> 1; stx ^= stx >> 2; stx ^= stx >> 4; stx ^= stx >> 8;
    // per-thread GF(2)-linear parts: scatter slot offset + reduction sign
    const int pts     = sw((int)cnot_perm((unsigned)tid));
    const int sgn_tid = __popc(tid) & 1;

    // ---- phase 1: encoding factors + ZYZ decomposition ----
    if (tid < NW) {
        float t = tanhf(x_raw[b * NW + tid]) * PI_F;
        senc[tid] = make_float2(cosf(0.5f * t), sinf(0.5f * t));
    }
    if (tid < NL * NW) {
        const int k = tid / NW, w = tid % NW;
        const float a0 = angles[(k * NW + w) * 3 + 0];
        const float a1 = angles[(k * NW + w) * 3 + 1];
        const float a2 = angles[(k * NW + w) * 3 + 2];
        const float c0 = cosf(0.5f * a0), s0 = sinf(0.5f * a0);
        const float c1 = cosf(0.5f * a1), s1 = sinf(0.5f * a1);
        float2 m00, m10;
        {
            const float2 ry00 = make_float2(c1, 0.f), ry01 = make_float2(-s1, 0.f);
            const float2 rx00 = make_float2(c0, 0.f), rx10 = make_float2(0.f, -s0);
            m00 = make_float2(ry00.x * rx00.x - ry00.y * rx00.y
                              + ry01.x * rx10.x - ry01.y * rx10.y,
                              ry00.x * rx00.y + ry00.y * rx00.x
                              + ry01.x * rx10.y + ry01.y * rx10.x);
            const float2 ry10 = make_float2(s1, 0.f), ry11 = make_float2(c1, 0.f);
            m10 = make_float2(ry10.x * rx00.x - ry10.y * rx00.y
                              + ry11.x * rx10.x - ry11.y * rx10.y,
                              ry10.x * rx00.y + ry10.y * rx00.x
                              + ry11.x * rx10.y + ry11.y * rx10.x);
        }
        const float2 em = make_float2(cosf(0.5f * a2), -sinf(0.5f * a2));
        const float2 ep = make_float2(em.x, -em.y);
        float2 u00 = cmul(em, m00);
        float2 u10 = cmul(ep, m10);
        float c  = sqrtf(u00.x * u00.x + u00.y * u00.y);
        float s  = sqrtf(u10.x * u10.x + u10.y * u10.y);
        float pp = -atan2f(u00.y, u00.x);
        float pm =  atan2f(u10.y, u10.x);
        float al = pp + pm, be = pp - pm;
        float t  = s / c;
        sU[tid * 2 + 0] = pk(t, t);
        sU[tid * 2 + 1] = pk(-t, -t);
        sAL[tid] = al;
        sBE[tid] = be;
        sC[tid]  = c;
    }
    __syncthreads();

    // ---- phase 2: diagonal tables + global scale ----
    if (tid < 32) {
        float a = 0.f;
#pragma unroll
        for (int bb = 0; bb < 5; bb++)
            if ((tid >> bb) & 1) a += sBE[13 - bb];
        sT0[tid] = make_float2(cosf(a), sinf(a));
    } else if (tid < 128) {
        const int bk = (tid - 32) >> 5, j = tid & 31;
        int sj = j; sj ^= sj >> 1; sj ^= sj >> 2; sj ^= sj >> 4;
        float a = 0.f;
#pragma unroll
        for (int q = 0; q < 5; q++)
            if ((j >> q) & 1) a += sAL[bk * NW + 4 - q];
#pragma unroll
        for (int q = 0; q < 4; q++)
            if ((sj >> q) & 1) a += sBE[(bk + 1) * NW + 4 - q];
        sTB[bk * 32 + j] = pk(cosf(a), cosf(a));
        sTP[bk * 32 + j] = pk(-sinf(a), sinf(a));
    } else if (tid < 131) {
        const int bk = tid - 128;
        float sb = 0.f;
#pragma unroll
        for (int m = 0; m < 9; m++) sb += sBE[(bk + 1) * NW + 13 - m];
        sSb[bk] = make_float2(cosf(sb), sinf(sb));
        float c13 = sBE[(bk + 1) * NW + 0];
        sZ13[bk] = make_float2(cosf(c13), sinf(c13));
    } else if (tid == 131) {
        float S = 1.f;
#pragma unroll
        for (int i = 0; i < NL * NW; i++) S *= sC[i];
        sS2[0] = S * S;
    }
    __syncthreads();

    u64 r[32];

    for (int k = 0; k < NL; k++) {
        const u64* Gk = sU + k * NW * 2;

        // ===== Pass A: i = tid*32 + j, wires 9..13 (j bits 4..0) =====
        // Slots [32*tid, 32*tid+32) are THREAD-private -> in-place safe,
        // store can interleave with the final butterfly.
        if (k == 0) {
            float v[32];
            float common = 1.f;
#pragma unroll
            for (int w = 0; w < 9; w++) {
                float2 cs = senc[w];
                common *= ((tid >> (8 - w)) & 1) ? cs.y : cs.x;
            }
            v[0] = common;
#pragma unroll
            for (int st = 0; st < 5; st++) {
                float2 cs = senc[9 + st];
#pragma unroll
                for (int kk = (1 << st) - 1; kk >= 0; kk--) {
                    float t = v[kk];
                    v[2 * kk + 1] = t * cs.y;
                    v[2 * kk]     = t * cs.x;
                }
            }
            float th0 = 0.f;
#pragma unroll
            for (int m = 0; m < 9; m++)
                if ((tid >> m) & 1) th0 += sBE[8 - m];
            float s0t, c0t; __sincosf(th0, &s0t, &c0t);
            const float2 z0 = make_float2(c0t, s0t);
#pragma unroll
            for (int j = 0; j < 32; j++) {
                float2 zj = cmul(z0, sT0[j]);
                r[j] = pk(v[j] * zj.x, v[j] * zj.y);
            }
            apply_gateT_h<0>(r,      Gk[13 * 2], Gk[13 * 2 + 1]);
            apply_gateT_h<1>(r,      Gk[12 * 2], Gk[12 * 2 + 1]);
            apply_gateT_h<2>(r,      Gk[11 * 2], Gk[11 * 2 + 1]);
            apply_gateT_h<3>(r,      Gk[10 * 2], Gk[10 * 2 + 1]);
            apply_gateT_h<0>(r + 16, Gk[13 * 2], Gk[13 * 2 + 1]);
            apply_gateT_h<1>(r + 16, Gk[12 * 2], Gk[12 * 2 + 1]);
            apply_gateT_h<2>(r + 16, Gk[11 * 2], Gk[11 * 2 + 1]);
            apply_gateT_h<3>(r + 16, Gk[10 * 2], Gk[10 * 2 + 1]);
        } else {
            const int m = tid & 31, base = tid * 32;
#pragma unroll
            for (int j = 0; j < 16; j++) r[j] = sv[base + (j ^ m)];
#pragma unroll
            for (int j = 16; j < 32; j++) r[j] = sv[base + (j ^ m)];
            apply_gateT_h<0>(r,      Gk[13 * 2], Gk[13 * 2 + 1]);
            apply_gateT_h<1>(r,      Gk[12 * 2], Gk[12 * 2 + 1]);
            apply_gateT_h<2>(r,      Gk[11 * 2], Gk[11 * 2 + 1]);
            apply_gateT_h<3>(r,      Gk[10 * 2], Gk[10 * 2 + 1]);
            apply_gateT_h<0>(r + 16, Gk[13 * 2], Gk[13 * 2 + 1]);
            apply_gateT_h<1>(r + 16, Gk[12 * 2], Gk[12 * 2 + 1]);
            apply_gateT_h<2>(r + 16, Gk[11 * 2], Gk[11 * 2 + 1]);
            apply_gateT_h<3>(r + 16, Gk[10 * 2], Gk[10 * 2 + 1]);
        }
        // fused gate<4> + store: STS interleaves with FFMA2
        {
            const int m = tid & 31, base = tid * 32;
            const u64 Tp = Gk[9 * 2], Tn = Gk[9 * 2 + 1];
#pragma unroll
            for (int p = 0; p < 16; p++) {
                u64 x0 = r[p], x1 = r[p + 16];
                u64 y0 = ffma2_(Tn, x1, x0);
                u64 y1 = ffma2_(Tp, x0, x1);
                sv[base + (p ^ m)]        = y0;
                sv[base + ((p + 16) ^ m)] = y1;
            }
        }
        __syncwarp();   // A-store -> B-load crosses threads within the warp

        // ===== Pass B: i = ((tid>>5)<<10)|(j<<5)|(tid&31), wires 4..8 =====
        // B load/store slots are thread-identical -> in-place safe.
        {
            const int hi = (tid >> 5) << 10, lo = tid & 31;
#pragma unroll
            for (int j = 0; j < 16; j++) r[j] = sv[hi + (j << 5) + (lo ^ j)];
#pragma unroll
            for (int j = 16; j < 32; j++) r[j] = sv[hi + (j << 5) + (lo ^ j)];
            apply_gateT_h<0>(r,      Gk[8 * 2], Gk[8 * 2 + 1]);
            apply_gateT_h<1>(r,      Gk[7 * 2], Gk[7 * 2 + 1]);
            apply_gateT_h<2>(r,      Gk[6 * 2], Gk[6 * 2 + 1]);
            apply_gateT_h<3>(r,      Gk[5 * 2], Gk[5 * 2 + 1]);
            apply_gateT_h<0>(r + 16, Gk[8 * 2], Gk[8 * 2 + 1]);
            apply_gateT_h<1>(r + 16, Gk[7 * 2], Gk[7 * 2 + 1]);
            apply_gateT_h<2>(r + 16, Gk[6 * 2], Gk[6 * 2 + 1]);
            apply_gateT_h<3>(r + 16, Gk[5 * 2], Gk[5 * 2 + 1]);
            // fused gate<4> + store
            const u64 Tp = Gk[4 * 2], Tn = Gk[4 * 2 + 1];
#pragma unroll
            for (int p = 0; p < 16; p++) {
                u64 x0 = r[p], x1 = r[p + 16];
                u64 y0 = ffma2_(Tn, x1, x0);
                u64 y1 = ffma2_(Tp, x0, x1);
                sv[hi + (p << 5) + (lo ^ p)]                = y0;
                sv[hi + ((p + 16) << 5) + (lo ^ (p + 16))]  = y1;
            }
        }
        __syncthreads();   // B-store -> C-load crosses warps

        // ===== Pass C: i = (j<<9)|tid, wires 0..3 on j bits 1..4; j bit 0 inert.
        if (k < NL - 1) {
            // V constants first (MUFU latency hides under C loads)
            float thA = 0.f, thB = 0.f;
#pragma unroll
            for (int m = 0; m < 9; m++) {
                if ((tid >> m) & 1) thA += sAL[k * NW + 13 - m];
                if ((stx >> m) & 1) thB += sBE[(k + 1) * NW + 13 - m];
            }
            float sa, ca, sb2, cb2;
            __sincosf(thA, &sa, &ca);
            __sincosf(thB, &sb2, &cb2);
            const float2 zA = make_float2(ca, sa);
            float2 A0 = cmul(zA, make_float2(cb2, sb2));
            float2 A1 = cmul(cmul(zA, make_float2(cb2, -sb2)), sSb[k]);
            const float2 z13 = sZ13[k];
            float2 A0x = cmul(A0, z13), A1x = cmul(A1, z13);
            float2 V00, V01, V10, V11;   // V[t][t']
            if (stx & 1) { V00 = A0x; V01 = A0;  V10 = A1x; V11 = A1;  }
            else         { V00 = A0;  V01 = A0x; V10 = A1;  V11 = A1x; }
            const u64 B00 = pk(V00.x, V00.x), P00 = pk(-V00.y, V00.y);
            const u64 B01 = pk(V01.x, V01.x), P01 = pk(-V01.y, V01.y);
            const u64 B10 = pk(V10.x, V10.x), P10 = pk(-V10.y, V10.y);
            const u64 B11 = pk(V11.x, V11.x), P11 = pk(-V11.y, V11.y);
            const u64* TBk = sTB + k * 32;
            const u64* TPk = sTP + k * 32;
            const int mid = (tid >> 5) & 15;

            u64* re = r;          // even-j stream
            u64* ro = r + 16;     // odd-j stream
#pragma unroll
            for (int q = 0; q < 16; q++)
                re[q] = sv[((2 * q) << 9) | (tid ^ mid)];
#pragma unroll
            for (int q = 0; q < 16; q++)
                ro[q] = sv[((2 * q + 1) << 9) | (tid ^ mid ^ 16)];
            apply_gateT_h<0>(re, Gk[3 * 2], Gk[3 * 2 + 1]);
            apply_gateT_h<1>(re, Gk[2 * 2], Gk[2 * 2 + 1]);
            apply_gateT_h<2>(re, Gk[1 * 2], Gk[1 * 2 + 1]);
            apply_gateT_h<3>(re, Gk[0 * 2], Gk[0 * 2 + 1]);
            apply_gateT_h<0>(ro, Gk[3 * 2], Gk[3 * 2 + 1]);
            apply_gateT_h<1>(ro, Gk[2 * 2], Gk[2 * 2 + 1]);
            apply_gateT_h<2>(ro, Gk[1 * 2], Gk[1 * 2 + 1]);
            apply_gateT_h<3>(ro, Gk[0 * 2], Gk[0 * 2 + 1]);
            // All C-loads CTA-wide must complete before ANY sv write
            // (scatter crosses warp regions).
            __syncthreads();
            // fused boundary-diagonal + scatter store: fma/STS mix
#pragma unroll
            for (int q = 0; q < 32; q++) {
                const int j  = (q & 15) * 2 + (q >> 4);
                const int t  = __popc(j) & 1;
                const int tp = __popc(j & 15) & 1;
                const u64 WB = t ? (tp ? B11 : B10) : (tp ? B01 : B00);
                const u64 WP = t ? (tp ? P11 : P10) : (tp ? P01 : P00);
                u64 val = dphase(dphase(r[q], TBk[j], TPk[j]), WB, WP);
                sv[sw((int)cnot_perm((unsigned)(j << 9))) ^ pts] = val;
            }
            __syncthreads();   // scatter -> next-layer A-load crosses warps
        } else {
            const int mid = (tid >> 5) & 15;
            u64* re = r;
            u64* ro = r + 16;
#pragma unroll
            for (int q = 0; q < 16; q++)
                re[q] = sv[((2 * q) << 9) | (tid ^ mid)];
#pragma unroll
            for (int q = 0; q < 16; q++)
                ro[q] = sv[((2 * q + 1) << 9) | (tid ^ mid ^ 16)];
            apply_gateT_h<0>(re, Gk[3 * 2], Gk[3 * 2 + 1]);
            apply_gateT_h<1>(re, Gk[2 * 2], Gk[2 * 2 + 1]);
            apply_gateT_h<2>(re, Gk[1 * 2], Gk[1 * 2 + 1]);
            apply_gateT_h<3>(re, Gk[0 * 2], Gk[0 * 2 + 1]);
            apply_gateT_h<0>(ro, Gk[3 * 2], Gk[3 * 2 + 1]);
            apply_gateT_h<1>(ro, Gk[2 * 2], Gk[2 * 2 + 1]);
            apply_gateT_h<2>(ro, Gk[1 * 2], Gk[1 * 2 + 1]);
            apply_gateT_h<3>(ro, Gk[0 * 2], Gk[0 * 2 + 1]);
            // <Z0>: per-j sign = parity(j&15) (compile-time), thread sign once.
            float acc = 0.f;
#pragma unroll
            for (int q = 0; q < 16; q++) {
                const int j = 2 * q;
                float re1, im1; unpk(re[q], re1, im1);
                float v1 = fmaf(re1, re1, im1 * im1);
                acc += (__popc(j & 15) & 1) ? -v1 : v1;
                const int j2 = 2 * q + 1;
                float re2, im2; unpk(ro[q], re2, im2);
                float v2 = fmaf(re2, re2, im2 * im2);
                acc += (__popc(j2 & 15) & 1) ? -v2 : v2;
            }
            acc = sgn_tid ? -acc : acc;
#pragma unroll
            for (int off = 16; off; off >>= 1)
                acc += __shfl_xor_sync(0xffffffffu, acc, off);
            if ((tid & 31) == 0) sred[tid >> 5] = acc;
            __syncthreads();
            if (tid < 32) {
                float v = (tid < 16) ? sred[tid] : 0.f;
#pragma unroll
                for (int off = 8; off; off >>= 1)
                    v += __shfl_xor_sync(0xffffffffu, v, off);
                if (tid == 0) out[b] = v * sS2[0];
            }
        }
    }
}

extern "C" void kernel_launch(void* const* d_in, const int* in_sizes, int n_in,
                              void* d_out, int out_size) {
    const float* x   = (const float*)d_in[0];
    const float* ang = (const float*)d_in[1];
    if (n_in >= 2 && in_sizes[0] == NL * NW * 3 && in_sizes[1] != NL * NW * 3) {
        const float* t = x; x = ang; ang = t;
    }
    float* out = (float*)d_out;

    const int smem_bytes =
        (NSTATE + NL * NW * 2 + 2 * 3 * 32) * 8
        + (32 + NW + 3 + 3) * 8
        + (3 * NL * NW + 1 + 16) * 4;
    cudaFuncSetAttribute(vqc_kernel, cudaFuncAttributeMaxDynamicSharedMemorySize,
                         smem_bytes);
    vqc_kernel<<<1024, THREADS, smem_bytes>>>(x, ang, out);
}

// round 14
// speedup vs baseline: 1.2775x; 1.0372x over previous
#include <cuda_runtime.h>
#include <math.h>

#define NW 14
#define NL 4
#define NSTATE (1 << NW)
#define THREADS 512
#define PI_F 3.14159265358979323846f

typedef unsigned long long u64;

// ---------- packed f32x2 helpers ----------
__device__ __forceinline__ u64 pk(float lo, float hi) {
    u64 r; asm("mov.b64 %0, {%1, %2};" : "=l"(r) : "f"(lo), "f"(hi)); return r;
}
__device__ __forceinline__ void unpk(u64 a, float& lo, float& hi) {
    asm("mov.b64 {%0, %1}, %2;" : "=f"(lo), "=f"(hi) : "l"(a));
}
__device__ __forceinline__ u64 swp(u64 a) {
    float lo, hi; unpk(a, lo, hi);
    u64 r; asm("mov.b64 %0, {%1, %2};" : "=l"(r) : "f"(hi), "f"(lo)); return r;
}
__device__ __forceinline__ u64 ffma2_(u64 a, u64 b, u64 c) {
    u64 d; asm("fma.rn.f32x2 %0, %1, %2, %3;" : "=l"(d) : "l"(a), "l"(b), "l"(c));
    return d;
}
__device__ __forceinline__ u64 fmul2_(u64 a, u64 b) {
    u64 d; asm("mul.rn.f32x2 %0, %1, %2;" : "=l"(d) : "l"(a), "l"(b));
    return d;
}

__device__ __forceinline__ float2 cmul(float2 a, float2 b) {
    return make_float2(a.x * b.x - a.y * b.y, a.x * b.y + a.y * b.x);
}

// Tangent-form RY butterfly on local bit L of a full 32-amp block.
template <int L>
__device__ __forceinline__ void apply_gateT(u64* r, u64 Tp, u64 Tn) {
#pragma unroll
    for (int p = 0; p < 16; p++) {
        const int lm = (1 << L) - 1;
        const int j0 = ((p & ~lm) << 1) | (p & lm);
        const int j1 = j0 | (1 << L);
        u64 x0 = r[j0], x1 = r[j1];
        r[j0] = ffma2_(Tn, x1, x0);
        r[j1] = ffma2_(Tp, x0, x1);
    }
}

// Tangent-form RY butterfly on local bit L (0..3) of a 16-amp half-block.
template <int L>
__device__ __forceinline__ void apply_gateT_h(u64* h, u64 Tp, u64 Tn) {
#pragma unroll
    for (int p = 0; p < 8; p++) {
        const int lm = (1 << L) - 1;
        const int j0 = ((p & ~lm) << 1) | (p & lm);
        const int j1 = j0 | (1 << L);
        u64 x0 = h[j0], x1 = h[j1];
        h[j0] = ffma2_(Tn, x1, x0);
        h[j1] = ffma2_(Tp, x0, x1);
    }
}

// Per-amp phase multiply: y = z*x, z as B=(zr,zr), P=(-zi,+zi).
__device__ __forceinline__ u64 dphase(u64 x, u64 B, u64 P) {
    return ffma2_(B, x, fmul2_(P, swp(x)));
}

// CNOT chain as GF(2)-linear basis permutation.
__device__ __forceinline__ unsigned cnot_perm(unsigned i) {
    unsigned s = i;
    s ^= s >> 1; s ^= s >> 2; s ^= s >> 4; s ^= s >> 8;
    return (s & 0x1FFFu) | (((s ^ (i >> 13)) & 1u) << 13);
}

// Scatter swizzle (pass-A layout): slot(i) = i ^ ((i>>5)&31). GF(2)-linear.
__device__ __forceinline__ int sw(int i) { return i ^ ((i >> 5) & 31); }

__global__ __launch_bounds__(THREADS, 1)
void vqc_kernel(const float* __restrict__ x_raw,
                const float* __restrict__ angles,
                float* __restrict__ out) {
    extern __shared__ unsigned char smem[];
    u64*    sv   = (u64*)smem;                 // [NSTATE]
    u64*    sU   = sv + NSTATE;                // [NL*NW*2]  Tp,Tn
    u64*    sTB  = sU + NL * NW * 2;           // [3*32] boundary diag table B
    u64*    sTP  = sTB + 3 * 32;               // [3*32] boundary diag table P
    float2* sT0  = (float2*)(sTP + 3 * 32);    // [32]  layer-0 D_R j-table
    float2* senc = sT0 + 32;                   // [NW]
    float2* sSb  = senc + NW;                  // [3]  e^{i sum(beta 5..13)}
    float2* sZ13 = sSb + 3;                    // [3]  e^{i beta(wire0)}
    float*  sAL  = (float*)(sZ13 + 3);         // [NL*NW] ZYZ alpha
    float*  sBE  = sAL + NL * NW;              // [NL*NW] ZYZ beta
    float*  sC   = sBE + NL * NW;              // [NL*NW] ZYZ cos
    float*  sS2  = sC + NL * NW;               // [1] total scale^2
    float*  sred = sS2 + 1;                    // [16]

    const int tid = threadIdx.x;
    const int b   = blockIdx.x;

    // suffix-xor of tid (9 bits)
    int stx = tid;
    stx ^= stx >> 1; stx ^= stx >> 2; stx ^= stx >> 4; stx ^= stx >> 8;
    // per-thread GF(2)-linear parts: scatter slot offset + reduction sign
    const int pts     = sw((int)cnot_perm((unsigned)tid));
    const int sgn_tid = __popc(tid) & 1;

    // ---- phase 1: encoding factors + ZYZ decomposition ----
    if (tid < NW) {
        float t = tanhf(x_raw[b * NW + tid]) * PI_F;
        senc[tid] = make_float2(cosf(0.5f * t), sinf(0.5f * t));
    }
    if (tid < NL * NW) {
        const int k = tid / NW, w = tid % NW;
        const float a0 = angles[(k * NW + w) * 3 + 0];
        const float a1 = angles[(k * NW + w) * 3 + 1];
        const float a2 = angles[(k * NW + w) * 3 + 2];
        const float c0 = cosf(0.5f * a0), s0 = sinf(0.5f * a0);
        const float c1 = cosf(0.5f * a1), s1 = sinf(0.5f * a1);
        float2 m00, m10;
        {
            const float2 ry00 = make_float2(c1, 0.f), ry01 = make_float2(-s1, 0.f);
            const float2 rx00 = make_float2(c0, 0.f), rx10 = make_float2(0.f, -s0);
            m00 = make_float2(ry00.x * rx00.x - ry00.y * rx00.y
                              + ry01.x * rx10.x - ry01.y * rx10.y,
                              ry00.x * rx00.y + ry00.y * rx00.x
                              + ry01.x * rx10.y + ry01.y * rx10.x);
            const float2 ry10 = make_float2(s1, 0.f), ry11 = make_float2(c1, 0.f);
            m10 = make_float2(ry10.x * rx00.x - ry10.y * rx00.y
                              + ry11.x * rx10.x - ry11.y * rx10.y,
                              ry10.x * rx00.y + ry10.y * rx00.x
                              + ry11.x * rx10.y + ry11.y * rx10.x);
        }
        const float2 em = make_float2(cosf(0.5f * a2), -sinf(0.5f * a2));
        const float2 ep = make_float2(em.x, -em.y);
        float2 u00 = cmul(em, m00);
        float2 u10 = cmul(ep, m10);
        float c  = sqrtf(u00.x * u00.x + u00.y * u00.y);
        float s  = sqrtf(u10.x * u10.x + u10.y * u10.y);
        float pp = -atan2f(u00.y, u00.x);
        float pm =  atan2f(u10.y, u10.x);
        float al = pp + pm, be = pp - pm;
        float t  = s / c;
        sU[tid * 2 + 0] = pk(t, t);
        sU[tid * 2 + 1] = pk(-t, -t);
        sAL[tid] = al;
        sBE[tid] = be;
        sC[tid]  = c;
    }
    __syncthreads();

    // ---- phase 2: diagonal tables + global scale ----
    if (tid < 32) {
        float a = 0.f;
#pragma unroll
        for (int bb = 0; bb < 5; bb++)
            if ((tid >> bb) & 1) a += sBE[13 - bb];
        sT0[tid] = make_float2(cosf(a), sinf(a));
    } else if (tid < 128) {
        const int bk = (tid - 32) >> 5, j = tid & 31;
        int sj = j; sj ^= sj >> 1; sj ^= sj >> 2; sj ^= sj >> 4;
        float a = 0.f;
#pragma unroll
        for (int q = 0; q < 5; q++)
            if ((j >> q) & 1) a += sAL[bk * NW + 4 - q];
#pragma unroll
        for (int q = 0; q < 4; q++)
            if ((sj >> q) & 1) a += sBE[(bk + 1) * NW + 4 - q];
        sTB[bk * 32 + j] = pk(cosf(a), cosf(a));
        sTP[bk * 32 + j] = pk(-sinf(a), sinf(a));
    } else if (tid < 131) {
        const int bk = tid - 128;
        float sb = 0.f;
#pragma unroll
        for (int m = 0; m < 9; m++) sb += sBE[(bk + 1) * NW + 13 - m];
        sSb[bk] = make_float2(cosf(sb), sinf(sb));
        float c13 = sBE[(bk + 1) * NW + 0];
        sZ13[bk] = make_float2(cosf(c13), sinf(c13));
    } else if (tid == 131) {
        // Global tangent-form scale. The last layer's wire-0 gate is DROPPED
        // (it commutes with the post-CNOT Z-string observable, and the
        // tangent butterfly preserves pair-norms up to 1/cos^2), so its cos
        // is excluded from the product.
        float S = 1.f;
#pragma unroll
        for (int i = 0; i < NL * NW; i++)
            if (i != (NL - 1) * NW + 0) S *= sC[i];
        sS2[0] = S * S;
    }
    __syncthreads();

    u64 r[32];

    for (int k = 0; k < NL; k++) {
        const u64* Gk = sU + k * NW * 2;

        // ===== Pass A: i = tid*32 + j, wires 9..13 (j bits 4..0) =====
        if (k == 0) {
            float v[32];
            float common = 1.f;
#pragma unroll
            for (int w = 0; w < 9; w++) {
                float2 cs = senc[w];
                common *= ((tid >> (8 - w)) & 1) ? cs.y : cs.x;
            }
            v[0] = common;
#pragma unroll
            for (int st = 0; st < 5; st++) {
                float2 cs = senc[9 + st];
#pragma unroll
                for (int kk = (1 << st) - 1; kk >= 0; kk--) {
                    float t = v[kk];
                    v[2 * kk + 1] = t * cs.y;
                    v[2 * kk]     = t * cs.x;
                }
            }
            float th0 = 0.f;
#pragma unroll
            for (int m = 0; m < 9; m++)
                if ((tid >> m) & 1) th0 += sBE[8 - m];
            float s0t, c0t; __sincosf(th0, &s0t, &c0t);
            const float2 z0 = make_float2(c0t, s0t);
#pragma unroll
            for (int j = 0; j < 32; j++) {
                float2 zj = cmul(z0, sT0[j]);
                r[j] = pk(v[j] * zj.x, v[j] * zj.y);
            }
            apply_gateT<0>(r, Gk[13 * 2], Gk[13 * 2 + 1]);
            apply_gateT<1>(r, Gk[12 * 2], Gk[12 * 2 + 1]);
            apply_gateT<2>(r, Gk[11 * 2], Gk[11 * 2 + 1]);
            apply_gateT<3>(r, Gk[10 * 2], Gk[10 * 2 + 1]);
        } else {
            const int m = tid & 31, base = tid * 32;
#pragma unroll
            for (int j = 0; j < 16; j++) r[j] = sv[base + (j ^ m)];
#pragma unroll
            for (int j = 16; j < 32; j++) r[j] = sv[base + (j ^ m)];
            apply_gateT_h<0>(r,      Gk[13 * 2], Gk[13 * 2 + 1]);
            apply_gateT_h<1>(r,      Gk[12 * 2], Gk[12 * 2 + 1]);
            apply_gateT_h<2>(r,      Gk[11 * 2], Gk[11 * 2 + 1]);
            apply_gateT_h<3>(r,      Gk[10 * 2], Gk[10 * 2 + 1]);
            apply_gateT_h<0>(r + 16, Gk[13 * 2], Gk[13 * 2 + 1]);
            apply_gateT_h<1>(r + 16, Gk[12 * 2], Gk[12 * 2 + 1]);
            apply_gateT_h<2>(r + 16, Gk[11 * 2], Gk[11 * 2 + 1]);
            apply_gateT_h<3>(r + 16, Gk[10 * 2], Gk[10 * 2 + 1]);
        }
        apply_gateT<4>(r, Gk[9 * 2], Gk[9 * 2 + 1]);
        {
            const int m = tid & 31, base = tid * 32;
#pragma unroll
            for (int j = 0; j < 32; j++) sv[base + (j ^ m)] = r[j];
        }
        __syncwarp();   // A-store -> B-load is warp-private

        // ===== Pass B: i = ((tid>>5)<<10)|(j<<5)|(tid&31), wires 4..8 =====
        {
            const int hi = (tid >> 5) << 10, lo = tid & 31;
#pragma unroll
            for (int j = 0; j < 16; j++) r[j] = sv[hi + (j << 5) + (lo ^ j)];
#pragma unroll
            for (int j = 16; j < 32; j++) r[j] = sv[hi + (j << 5) + (lo ^ j)];
            apply_gateT_h<0>(r,      Gk[8 * 2], Gk[8 * 2 + 1]);
            apply_gateT_h<1>(r,      Gk[7 * 2], Gk[7 * 2 + 1]);
            apply_gateT_h<2>(r,      Gk[6 * 2], Gk[6 * 2 + 1]);
            apply_gateT_h<3>(r,      Gk[5 * 2], Gk[5 * 2 + 1]);
            apply_gateT_h<0>(r + 16, Gk[8 * 2], Gk[8 * 2 + 1]);
            apply_gateT_h<1>(r + 16, Gk[7 * 2], Gk[7 * 2 + 1]);
            apply_gateT_h<2>(r + 16, Gk[6 * 2], Gk[6 * 2 + 1]);
            apply_gateT_h<3>(r + 16, Gk[5 * 2], Gk[5 * 2 + 1]);
            apply_gateT<4>(r, Gk[4 * 2], Gk[4 * 2 + 1]);
#pragma unroll
            for (int j = 0; j < 32; j++) sv[hi + (j << 5) + (lo ^ j)] = r[j];
        }
        __syncthreads();   // B-store -> C-load crosses warps

        // ===== Pass C: i = (j<<9)|tid, wires 0..3 on j bits 1..4; j bit 0 inert.
        if (k < NL - 1) {
            // V constants first (MUFU latency hides under C loads)
            float thA = 0.f, thB = 0.f;
#pragma unroll
            for (int m = 0; m < 9; m++) {
                if ((tid >> m) & 1) thA += sAL[k * NW + 13 - m];
                if ((stx >> m) & 1) thB += sBE[(k + 1) * NW + 13 - m];
            }
            float sa, ca, sb2, cb2;
            __sincosf(thA, &sa, &ca);
            __sincosf(thB, &sb2, &cb2);
            const float2 zA = make_float2(ca, sa);
            float2 A0 = cmul(zA, make_float2(cb2, sb2));
            float2 A1 = cmul(cmul(zA, make_float2(cb2, -sb2)), sSb[k]);
            const float2 z13 = sZ13[k];
            float2 A0x = cmul(A0, z13), A1x = cmul(A1, z13);
            float2 V00, V01, V10, V11;   // V[t][t']
            if (stx & 1) { V00 = A0x; V01 = A0;  V10 = A1x; V11 = A1;  }
            else         { V00 = A0;  V01 = A0x; V10 = A1;  V11 = A1x; }
            const u64 B00 = pk(V00.x, V00.x), P00 = pk(-V00.y, V00.y);
            const u64 B01 = pk(V01.x, V01.x), P01 = pk(-V01.y, V01.y);
            const u64 B10 = pk(V10.x, V10.x), P10 = pk(-V10.y, V10.y);
            const u64 B11 = pk(V11.x, V11.x), P11 = pk(-V11.y, V11.y);
            const u64* TBk = sTB + k * 32;
            const u64* TPk = sTP + k * 32;
            const int mid = (tid >> 5) & 15;

            u64* re = r;          // even-j stream
            u64* ro = r + 16;     // odd-j stream
#pragma unroll
            for (int q = 0; q < 16; q++)
                re[q] = sv[((2 * q) << 9) | (tid ^ mid)];
#pragma unroll
            for (int q = 0; q < 16; q++)
                ro[q] = sv[((2 * q + 1) << 9) | (tid ^ mid ^ 16)];
            // gates + diag, all in registers (diag BEFORE the race barrier:
            // keep the barrier-serialized tail as short as possible)
            apply_gateT_h<0>(re, Gk[3 * 2], Gk[3 * 2 + 1]);
            apply_gateT_h<1>(re, Gk[2 * 2], Gk[2 * 2 + 1]);
            apply_gateT_h<2>(re, Gk[1 * 2], Gk[1 * 2 + 1]);
            apply_gateT_h<3>(re, Gk[0 * 2], Gk[0 * 2 + 1]);
            apply_gateT_h<0>(ro, Gk[3 * 2], Gk[3 * 2 + 1]);
            apply_gateT_h<1>(ro, Gk[2 * 2], Gk[2 * 2 + 1]);
            apply_gateT_h<2>(ro, Gk[1 * 2], Gk[1 * 2 + 1]);
            apply_gateT_h<3>(ro, Gk[0 * 2], Gk[0 * 2 + 1]);
#pragma unroll
            for (int q = 0; q < 32; q++) {
                const int j  = (q & 15) * 2 + (q >> 4);
                const int t  = __popc(j) & 1;
                const int tp = __popc(j & 15) & 1;
                const u64 WB = t ? (tp ? B11 : B10) : (tp ? B01 : B00);
                const u64 WP = t ? (tp ? P11 : P10) : (tp ? P01 : P00);
                r[q] = dphase(dphase(r[q], TBk[j], TPk[j]), WB, WP);
            }
            // All C-loads CTA-wide must complete before ANY scatter store
            // (the scatter crosses warp regions).
            __syncthreads();
#pragma unroll
            for (int q = 0; q < 32; q++) {
                const int j = (q & 15) * 2 + (q >> 4);
                sv[sw((int)cnot_perm((unsigned)(j << 9))) ^ pts] = r[q];
            }
            __syncthreads();   // scatter -> next-layer A-load crosses warps
        } else {
            const int mid = (tid >> 5) & 15;
            u64* re = r;
            u64* ro = r + 16;
#pragma unroll
            for (int q = 0; q < 16; q++)
                re[q] = sv[((2 * q) << 9) | (tid ^ mid)];
#pragma unroll
            for (int q = 0; q < 16; q++)
                ro[q] = sv[((2 * q + 1) << 9) | (tid ^ mid ^ 16)];
            // Last layer: wires 3,2,1 only — the wire-0 gate (local bit 4)
            // commutes with the Z-string observable and is dropped (its
            // 1/cos^2 factor is excluded from sS2).
            apply_gateT_h<0>(re, Gk[3 * 2], Gk[3 * 2 + 1]);
            apply_gateT_h<1>(re, Gk[2 * 2], Gk[2 * 2 + 1]);
            apply_gateT_h<2>(re, Gk[1 * 2], Gk[1 * 2 + 1]);
            apply_gateT_h<0>(ro, Gk[3 * 2], Gk[3 * 2 + 1]);
            apply_gateT_h<1>(ro, Gk[2 * 2], Gk[2 * 2 + 1]);
            apply_gateT_h<2>(ro, Gk[1 * 2], Gk[1 * 2 + 1]);
            // <Z0>: per-j sign = parity(j&15) (compile-time), thread sign once.
            float acc = 0.f;
#pragma unroll
            for (int q = 0; q < 16; q++) {
                const int j = 2 * q;
                float re1, im1; unpk(re[q], re1, im1);
                float v1 = fmaf(re1, re1, im1 * im1);
                acc += (__popc(j & 15) & 1) ? -v1 : v1;
                const int j2 = 2 * q + 1;
                float re2, im2; unpk(ro[q], re2, im2);
                float v2 = fmaf(re2, re2, im2 * im2);
                acc += (__popc(j2 & 15) & 1) ? -v2 : v2;
            }
            acc = sgn_tid ? -acc : acc;
#pragma unroll
            for (int off = 16; off; off >>= 1)
                acc += __shfl_xor_sync(0xffffffffu, acc, off);
            if ((tid & 31) == 0) sred[tid >> 5] = acc;
            __syncthreads();
            if (tid < 32) {
                float v = (tid < 16) ? sred[tid] : 0.f;
#pragma unroll
                for (int off = 8; off; off >>= 1)
                    v += __shfl_xor_sync(0xffffffffu, v, off);
                if (tid == 0) out[b] = v * sS2[0];
            }
        }
    }
}

extern "C" void kernel_launch(void* const* d_in, const int* in_sizes, int n_in,
                              void* d_out, int out_size) {
    const float* x   = (const float*)d_in[0];
    const float* ang = (const float*)d_in[1];
    if (n_in >= 2 && in_sizes[0] == NL * NW * 3 && in_sizes[1] != NL * NW * 3) {
        const float* t = x; x = ang; ang = t;
    }
    float* out = (float*)d_out;

    const int smem_bytes =
        (NSTATE + NL * NW * 2 + 2 * 3 * 32) * 8
        + (32 + NW + 3 + 3) * 8
        + (3 * NL * NW + 1 + 16) * 4;
    cudaFuncSetAttribute(vqc_kernel, cudaFuncAttributeMaxDynamicSharedMemorySize,
                         smem_bytes);
    vqc_kernel<<<1024, THREADS, smem_bytes>>>(x, ang, out);
}